// round 6
// baseline (speedup 1.0000x reference)
#include <cuda_runtime.h>
#include <cstdint>

// Shape fixed by dataset: B=16, T=8192, N=32, depth=31.
constexpr int N_STACK = 32;
constexpr int DEPTH   = 31;
constexpr int OPSROW  = DEPTH * 5;      // 155 floats per (b,t)
constexpr int TPB     = 128;
constexpr int WARPS   = TPB / 32;
constexpr int CCOL    = 33;             // padded column stride (bank-conflict-free)
constexpr int BUFF    = 32 * CCOL;      // 1056 floats: holds a 30-col ops chunk or 32-col logm tile

__device__ __forceinline__ uint32_t smem_u32(const void* p) {
    return (uint32_t)__cvta_generic_to_shared(p);
}
__device__ __forceinline__ void cp_async4(uint32_t dst, const float* src) {
    asm volatile("cp.async.ca.shared.global [%0], [%1], 4;" :: "r"(dst), "l"(src));
}
__device__ __forceinline__ void cp_commit() { asm volatile("cp.async.commit_group;"); }
template<int N>
__device__ __forceinline__ void cp_wait() {
    asm volatile("cp.async.wait_group %0;" :: "n"(N) : "memory");
}

__device__ __forceinline__ float tanh10(float x) {   // 10*tanh(x/10)
    float r;
    asm("tanh.approx.f32 %0, %1;" : "=f"(r) : "f"(x * 0.1f));
    return r * 10.0f;
}

// Stage one ops chunk (F floats per thread-row) into transposed smem [col][row].
template<int F>
__device__ __forceinline__ void stage(float* buf, const float* __restrict__ g, int lane) {
    uint32_t b = smem_u32(buf);
#pragma unroll
    for (int it = 0; it < F; it++) {
        int lin = it * 32 + lane;
        int row = lin / F;               // compile-time divisor
        int col = lin - row * F;
        cp_async4(b + (uint32_t)(col * CCOL + row) * 4u, g + row * OPSROW + col);
    }
    cp_commit();
}

struct State { float rs, rl, SS; };

// One soft-op step; K compile-time. sec = original (l[30-K], sign bit), top = running state.
template<int K>
__device__ __forceinline__ void do_step(const float* buf, int kk, int lane,
                                        const float* l, unsigned smask, State& st) {
    constexpr int SI = 30 - K;
    float sl = l[SI];
    float ss = (smask >> SI) & 1u ? -1.0f : 1.0f;
    float rs = st.rs, rl = st.rl;

    float p0 = buf[(kk * 5 + 0) * CCOL + lane];
    float p1 = buf[(kk * 5 + 1) * CCOL + lane];
    float p2 = buf[(kk * 5 + 2) * CCOL + lane];
    float p3 = buf[(kk * 5 + 3) * CCOL + lane];
    float p4 = buf[(kk * 5 + 4) * CCOL + lane];

    // shared magnitude math for add & sub (signs don't change the log values)
    float mx  = fmaxf(sl, rl), mn = fminf(sl, rl);
    float ed  = __expf(mn - mx);                     // e^{mn-mx} in (0,1]
    float lse = mx + __logf(1.0f + ed);
    float C1  = tanh10(tanh10(lse));                 // same-sign: double clip (as ref)
    // exp(clip(d,-10,-.001)) == clip(exp(d)) since exp is monotone
    float edc  = fminf(fmaxf(ed, 4.5399930e-5f), 0.99900050f);
    float diff = __logf(1.0f - edc);
    bool  zr   = (mn == mx);
    float C2   = zr ? 0.0f : tanh10(mx + diff);      // opposite-sign: single clip

    bool  bx   = (sl >= rl);
    float srs  = ss * rs;
    bool  same = (srs > 0.0f);
    float bsA  = bx ? ss : rs;                       // big sign when y = +rs
    float bsS  = bx ? ss : -rs;                      // big sign when y = -rs

    float aS, aL, sS, sL;
    if (same) { aS = ss;               aL = C1;  sS = zr ? 0.0f : bsS;  sL = C2; }
    else      { aS = zr ? 0.0f : bsA;  aL = C2;  sS = ss;               sL = C1; }
    // ss is exactly +/-1; only rs can be zero (only_x case of the reference)
    if (rs == 0.0f) { aS = ss; aL = tanh10(sl); sS = ss; sL = aL; }

    float mulL = tanh10(sl + rl);
    float divL = tanh10(sl - rl);

    float nsgn = aS * p0 + sS * p1 + srs * (p2 + p3) + ss * p4;
    float nlog = aL * p0 + sL * p1 + mulL * p2 + divL * p3 + sl * p4;

    // RMS rescale over [original prefix of len 31-K, nlog]
    constexpr float cs_inv = 1.0f / (float)(N_STACK - K);
    float msq   = fmaf(nlog, nlog, st.SS) * cs_inv + 1e-6f;
    float scale = fminf(10.0f * rsqrtf(msq), 1.0f);

    st.rl = nlog * scale;
    st.rs = nsgn;
    st.SS = fmaf(-sl, sl, st.SS);                    // drop sec from prefix
}

template<int K0, int NS>
__device__ __forceinline__ void compute_chunk(const float* buf, int lane,
                                              const float* l, unsigned smask, State& st) {
#pragma unroll
    for (int kk = 0; kk < NS; kk++) {
        switch (K0 + kk) {   // keep K compile-time under the unrolled loop
#define CASE(KK) case KK: do_step<KK>(buf, kk, lane, l, smask, st); break;
            CASE(0) CASE(1) CASE(2) CASE(3) CASE(4) CASE(5) CASE(6) CASE(7)
            CASE(8) CASE(9) CASE(10) CASE(11) CASE(12) CASE(13) CASE(14) CASE(15)
            CASE(16) CASE(17) CASE(18) CASE(19) CASE(20) CASE(21) CASE(22) CASE(23)
            CASE(24) CASE(25) CASE(26) CASE(27) CASE(28) CASE(29) CASE(30)
#undef CASE
        }
    }
}

__global__ __launch_bounds__(TPB, 6)
void stack_machine_kernel(const float* __restrict__ sgn,
                          const float* __restrict__ logm,
                          const float* __restrict__ ops,
                          float* __restrict__ out,
                          int bt_total) {
    __shared__ float SM[WARPS * 2 * BUFF];
    const int tid  = threadIdx.x;
    const int lane = tid & 31;
    const int w    = tid >> 5;
    const int warpBt = blockIdx.x * TPB + w * 32;
    const int bt     = warpBt + lane;

    float* buf0 = SM + w * 2 * BUFF;
    float* buf1 = buf0 + BUFF;
    const float* gops = ops + (size_t)warpBt * OPSROW;

    // Kick off ops chunk 0 into buf1 immediately (latency hidden by setup below).
    stage<25>(buf1, gops, lane);                       // group 0

    // ---- logm: warp-coalesced float4 loads -> transpose through buf0 -> regs ----
    const float4* gl4 = reinterpret_cast<const float4*>(logm + (size_t)warpBt * N_STACK);
#pragma unroll
    for (int it = 0; it < 8; it++) {
        float4 v = __ldg(gl4 + it * 32 + lane);
        int lin = it * 32 + lane;
        int row = lin >> 3, c4 = lin & 7;
        buf0[(c4 * 4 + 0) * CCOL + row] = v.x;
        buf0[(c4 * 4 + 1) * CCOL + row] = v.y;
        buf0[(c4 * 4 + 2) * CCOL + row] = v.z;
        buf0[(c4 * 4 + 3) * CCOL + row] = v.w;
    }
    __syncwarp();
    float l[N_STACK];
    State st; st.SS = 0.0f;
#pragma unroll
    for (int c = 0; c < N_STACK; c++) {
        l[c] = buf0[c * CCOL + lane];
        if (c < N_STACK - 1) st.SS = fmaf(l[c], l[c], st.SS);  // SS covers 0..30
    }
    st.rl = l[N_STACK - 1];
    __syncwarp();   // all lanes done reading buf0 before chunk 1 overwrites it

    // ---- sgn: coalesced row loads + ballot -> per-thread sign bitmask ----
    unsigned smask = 0;
    {
        const float* gs = sgn + (size_t)warpBt * N_STACK;
#pragma unroll
        for (int it = 0; it < N_STACK; it++) {
            float f = __ldg(gs + it * 32 + lane);
            unsigned m = __ballot_sync(0xffffffffu, f < 0.0f);
            if (lane == it) smask = m;
        }
    }
    st.rs = (smask >> 31) & 1u ? -1.0f : 1.0f;

    // ---- double-buffered chunk pipeline: 5x5 steps + 1x6 steps ----
    stage<25>(buf0, gops + 25, lane);                  // group 1 (chunk 1)
    cp_wait<1>(); __syncwarp();
    compute_chunk<0, 5>(buf1, lane, l, smask, st);     // chunk 0

    stage<25>(buf1, gops + 50, lane);                  // group 2
    cp_wait<1>(); __syncwarp();
    compute_chunk<5, 5>(buf0, lane, l, smask, st);     // chunk 1

    stage<25>(buf0, gops + 75, lane);                  // group 3
    cp_wait<1>(); __syncwarp();
    compute_chunk<10, 5>(buf1, lane, l, smask, st);    // chunk 2

    stage<25>(buf1, gops + 100, lane);                 // group 4
    cp_wait<1>(); __syncwarp();
    compute_chunk<15, 5>(buf0, lane, l, smask, st);    // chunk 3

    stage<30>(buf0, gops + 125, lane);                 // group 5 (chunk 5: steps 25..30)
    cp_wait<1>(); __syncwarp();
    compute_chunk<20, 5>(buf1, lane, l, smask, st);    // chunk 4

    cp_wait<0>(); __syncwarp();
    compute_chunk<25, 6>(buf0, lane, l, smask, st);    // chunk 5

    out[bt]            = st.rs;   // (sign, log) stacked -> (2, B*T); coalesced
    out[bt_total + bt] = st.rl;
}

extern "C" void kernel_launch(void* const* d_in, const int* in_sizes, int n_in,
                              void* d_out, int out_size) {
    const float* sgn  = (const float*)d_in[0];
    const float* logm = (const float*)d_in[1];
    const float* ops  = (const float*)d_in[2];
    float* out = (float*)d_out;

    int bt_total = out_size / 2;                 // 131072; divisible by TPB
    int blocks = bt_total / TPB;                 // 1024
    stack_machine_kernel<<<blocks, TPB>>>(sgn, logm, ops, out, bt_total);
}

// round 7
// speedup vs baseline: 2.9365x; 2.9365x over previous
#include <cuda_runtime.h>
#include <cstdint>

// Shape fixed by dataset: B=16, T=8192, N=32, depth=31.
constexpr int N_STACK = 32;
constexpr int DEPTH   = 31;
constexpr int OPSROW  = DEPTH * 5;   // 155 floats per (b,t) row
constexpr int TPB     = 128;
constexpr int LPAD    = 33;          // per-thread smem log row stride (conflict-free)

__constant__ float CS_INV[DEPTH] = {
    1.0f/32, 1.0f/31, 1.0f/30, 1.0f/29, 1.0f/28, 1.0f/27, 1.0f/26, 1.0f/25,
    1.0f/24, 1.0f/23, 1.0f/22, 1.0f/21, 1.0f/20, 1.0f/19, 1.0f/18, 1.0f/17,
    1.0f/16, 1.0f/15, 1.0f/14, 1.0f/13, 1.0f/12, 1.0f/11, 1.0f/10, 1.0f/9,
    1.0f/8,  1.0f/7,  1.0f/6,  1.0f/5,  1.0f/4,  1.0f/3,  1.0f/2 };

__device__ __forceinline__ float tanh10(float x) {   // 10*tanh(x/10)
    float r;
    asm("tanh.approx.f32 %0, %1;" : "=f"(r) : "f"(x * 0.1f));
    return r * 10.0f;
}

struct State { float rs, rl, SS; };

// One soft-op step. sec = original stack entry; top = running (st.rs, st.rl). k runtime.
__device__ __forceinline__ void do_step(int k, const float* lrow, unsigned smask,
                                        float p0, float p1, float p2, float p3, float p4,
                                        State& st) {
    int   si = 30 - k;
    float sl = lrow[si];                                   // LDS, conflict-free
    float ss = (smask >> si) & 1u ? -1.0f : 1.0f;
    float rs = st.rs, rl = st.rl;

    // shared magnitude math for add & sub (signs don't change the log values)
    float mx  = fmaxf(sl, rl), mn = fminf(sl, rl);
    float ed  = __expf(mn - mx);                           // e^{mn-mx} in (0,1]
    float lse = mx + __logf(1.0f + ed);
    float C1  = tanh10(tanh10(lse));                       // same-sign: double clip (as ref)
    // exp(clip(d,-10,-.001)) == clip(exp(d), e^-10, e^-.001)  (exp monotone)
    float edc  = fminf(fmaxf(ed, 4.5399930e-5f), 0.99900050f);
    float diff = __logf(1.0f - edc);
    bool  zr   = (mn == mx);
    float C2   = zr ? 0.0f : tanh10(mx + diff);            // opposite-sign: single clip

    bool  bx   = (sl >= rl);
    float srs  = ss * rs;
    bool  same = (srs > 0.0f);
    float bsA  = bx ? ss : rs;                             // big sign when y = +rs
    float bsS  = bx ? ss : -rs;                            // big sign when y = -rs

    float aS, aL, sS, sL;
    if (same) { aS = ss;               aL = C1;  sS = zr ? 0.0f : bsS;  sL = C2; }
    else      { aS = zr ? 0.0f : bsA;  aL = C2;  sS = ss;               sL = C1; }
    // ss is exactly +/-1 (original sign); only rs can be zero (only_x case)
    if (rs == 0.0f) { aS = ss; aL = tanh10(sl); sS = ss; sL = aL; }

    float mulL = tanh10(sl + rl);
    float divL = tanh10(sl - rl);

    float nsgn = aS * p0 + sS * p1 + srs * (p2 + p3) + ss * p4;
    float nlog = aL * p0 + sL * p1 + mulL * p2 + divL * p3 + sl * p4;

    // RMS rescale over [original prefix of len 31-k, nlog]
    float msq   = fmaf(nlog, nlog, st.SS) * CS_INV[k] + 1e-6f;
    float scale = fminf(10.0f * rsqrtf(msq), 1.0f);

    st.rl = nlog * scale;
    st.rs = nsgn;
    st.SS = fmaf(-sl, sl, st.SS);                          // drop sec from prefix
}

__device__ __forceinline__ float comp(const float4& v, int j) {
    return j == 0 ? v.x : j == 1 ? v.y : j == 2 ? v.z : v.w;
}

// Logical stream element I of the current group, read directly from live quads.
// O == 0: I in [0,20) -> quad I/4.  O > 0: I<4 -> carry, else quad (I-4)/4.
template<int I, int O>
__device__ __forceinline__ float pick(const float4& carry, const float4& c0, const float4& c1,
                                      const float4& c2, const float4& c3, const float4& c4) {
    if constexpr (O == 0) {
        constexpr int q = I / 4, j = I % 4;
        if constexpr (q == 0) return comp(c0, j);
        else if constexpr (q == 1) return comp(c1, j);
        else if constexpr (q == 2) return comp(c2, j);
        else if constexpr (q == 3) return comp(c3, j);
        else return comp(c4, j);
    } else {
        if constexpr (I < 4) return comp(carry, I);
        else {
            constexpr int q = (I - 4) / 4, j = (I - 4) % 4;
            if constexpr (q == 0) return comp(c0, j);
            else if constexpr (q == 1) return comp(c1, j);
            else if constexpr (q == 2) return comp(c2, j);
            else if constexpr (q == 3) return comp(c3, j);
            else return comp(c4, j);
        }
    }
}

// O = floats of the previous row inside the first aligned 16B vector of this row.
template<int O>
__device__ __forceinline__ void run(int bt, int bt_total,
                                    const float* __restrict__ sgn,
                                    const float* __restrict__ logm,
                                    const float* __restrict__ ops,
                                    float* __restrict__ out,
                                    float* lrow) {
    // ---- ops: kick off carry + group-0 quads FIRST (deepest latency) ----
    const float4* vp = reinterpret_cast<const float4*>(ops + (size_t)bt * OPSROW - O);
    float4 carry = make_float4(0.f, 0.f, 0.f, 0.f);
    if (O > 0) { carry = __ldg(vp); vp++; }
    float4 c0 = __ldg(vp + 0), c1 = __ldg(vp + 1), c2 = __ldg(vp + 2),
           c3 = __ldg(vp + 3), c4 = __ldg(vp + 4);
    vp += 5;

    // ---- logs: one 128B line per thread; square-sum + stash in smem row ----
    const float4* Lv = reinterpret_cast<const float4*>(logm + (size_t)bt * N_STACK);
    const float4* Sv = reinterpret_cast<const float4*>(sgn  + (size_t)bt * N_STACK);
    State st; st.SS = 0.0f;
    unsigned smask = 0;
#pragma unroll
    for (int i = 0; i < 8; i++) {
        float4 v = __ldg(Lv + i);
        lrow[4 * i + 0] = v.x; lrow[4 * i + 1] = v.y;
        lrow[4 * i + 2] = v.z; lrow[4 * i + 3] = v.w;
        st.SS = fmaf(v.x, v.x, st.SS);
        st.SS = fmaf(v.y, v.y, st.SS);
        st.SS = fmaf(v.z, v.z, st.SS);
        if (i < 7) st.SS = fmaf(v.w, v.w, st.SS);  // SS covers indices 0..30 only
        else       st.rl = v.w;                    // initial top log

        float4 s = __ldg(Sv + i);
        smask |= (s.x < 0.0f ? 1u : 0u) << (4 * i + 0);
        smask |= (s.y < 0.0f ? 1u : 0u) << (4 * i + 1);
        smask |= (s.z < 0.0f ? 1u : 0u) << (4 * i + 2);
        smask |= (s.w < 0.0f ? 1u : 0u) << (4 * i + 3);
    }
    st.rs = (smask >> 31) & 1u ? -1.0f : 1.0f;

    // ---- 7 groups x 4 steps, depth-2 software pipeline ----
#pragma unroll 1
    for (int g = 0; g < 7; g++) {
        // Prefetch group g+1 while computing group g (predicated off on last group).
        float4 n0, n1, n2, n3, n4;
        bool more = (g < 6);
        if (more) {
            n0 = __ldg(vp + 0); n1 = __ldg(vp + 1); n2 = __ldg(vp + 2);
            n3 = __ldg(vp + 3); n4 = __ldg(vp + 4);
            vp += 5;
        }

        int k0 = 4 * g;
#pragma unroll
        for (int kk = 0; kk < 4; kk++) {
            // I = O + 5*kk + j, all compile-time
            switch (kk) {
              case 0: do_step(k0 + 0, lrow, smask,
                        pick<O+0,O>(carry,c0,c1,c2,c3,c4),  pick<O+1,O>(carry,c0,c1,c2,c3,c4),
                        pick<O+2,O>(carry,c0,c1,c2,c3,c4),  pick<O+3,O>(carry,c0,c1,c2,c3,c4),
                        pick<O+4,O>(carry,c0,c1,c2,c3,c4),  st); break;
              case 1: do_step(k0 + 1, lrow, smask,
                        pick<O+5,O>(carry,c0,c1,c2,c3,c4),  pick<O+6,O>(carry,c0,c1,c2,c3,c4),
                        pick<O+7,O>(carry,c0,c1,c2,c3,c4),  pick<O+8,O>(carry,c0,c1,c2,c3,c4),
                        pick<O+9,O>(carry,c0,c1,c2,c3,c4),  st); break;
              case 2: do_step(k0 + 2, lrow, smask,
                        pick<O+10,O>(carry,c0,c1,c2,c3,c4), pick<O+11,O>(carry,c0,c1,c2,c3,c4),
                        pick<O+12,O>(carry,c0,c1,c2,c3,c4), pick<O+13,O>(carry,c0,c1,c2,c3,c4),
                        pick<O+14,O>(carry,c0,c1,c2,c3,c4), st); break;
              case 3: do_step(k0 + 3, lrow, smask,
                        pick<O+15,O>(carry,c0,c1,c2,c3,c4), pick<O+16,O>(carry,c0,c1,c2,c3,c4),
                        pick<O+17,O>(carry,c0,c1,c2,c3,c4), pick<O+18,O>(carry,c0,c1,c2,c3,c4),
                        pick<O+19,O>(carry,c0,c1,c2,c3,c4), st); break;
            }
        }

        carry = c4;                       // last quad of this group feeds the next
        if (more) { c0 = n0; c1 = n1; c2 = n2; c3 = n3; c4 = n4; }
    }

    // ---- epilogue: steps 28..30 (row floats 140..154) ----
    {
        float f[20];
#pragma unroll
        for (int i = 0; i < 20; i++) f[i] = 0.0f;
        if (O == 0) {
            float4 v0 = __ldg(vp + 0), v1 = __ldg(vp + 1), v2 = __ldg(vp + 2), v3 = __ldg(vp + 3);
            f[0]  = v0.x; f[1]  = v0.y; f[2]  = v0.z; f[3]  = v0.w;
            f[4]  = v1.x; f[5]  = v1.y; f[6]  = v1.z; f[7]  = v1.w;
            f[8]  = v2.x; f[9]  = v2.y; f[10] = v2.z; f[11] = v2.w;
            f[12] = v3.x; f[13] = v3.y; f[14] = v3.z;
        } else if (O == 1) {
            float4 v0 = __ldg(vp + 0), v1 = __ldg(vp + 1), v2 = __ldg(vp + 2);
            f[0] = carry.x; f[1] = carry.y; f[2] = carry.z; f[3] = carry.w;
            f[4]  = v0.x; f[5]  = v0.y; f[6]  = v0.z; f[7]  = v0.w;
            f[8]  = v1.x; f[9]  = v1.y; f[10] = v1.z; f[11] = v1.w;
            f[12] = v2.x; f[13] = v2.y; f[14] = v2.z; f[15] = v2.w;
        } else {  // O == 2 or 3 (overreads stay inside the ops array: last row has O==1)
            float4 v0 = __ldg(vp + 0), v1 = __ldg(vp + 1), v2 = __ldg(vp + 2), v3 = __ldg(vp + 3);
            f[0] = carry.x; f[1] = carry.y; f[2] = carry.z; f[3] = carry.w;
            f[4]  = v0.x; f[5]  = v0.y; f[6]  = v0.z; f[7]  = v0.w;
            f[8]  = v1.x; f[9]  = v1.y; f[10] = v1.z; f[11] = v1.w;
            f[12] = v2.x; f[13] = v2.y; f[14] = v2.z; f[15] = v2.w;
            f[16] = v3.x; f[17] = v3.y; f[18] = v3.z; f[19] = v3.w;
        }
#pragma unroll
        for (int kk = 0; kk < 3; kk++)
            do_step(28 + kk, lrow, smask,
                    f[O + 5 * kk + 0], f[O + 5 * kk + 1], f[O + 5 * kk + 2],
                    f[O + 5 * kk + 3], f[O + 5 * kk + 4], st);
    }

    out[bt]            = st.rs;   // (sign, log) stacked -> (2, B*T)
    out[bt_total + bt] = st.rl;
}

__global__ __launch_bounds__(TPB, 5)
void stack_machine_kernel(const float* __restrict__ sgn,
                          const float* __restrict__ logm,
                          const float* __restrict__ ops,
                          float* __restrict__ out,
                          int bt_total) {
    __shared__ float LBUF[TPB * LPAD];
    const int tid = threadIdx.x;
    const int c   = blockIdx.x & 3;                       // alignment class (bt mod 4)
    const int bt  = 4 * ((blockIdx.x >> 2) * TPB + tid) + c;
    float* lrow = LBUF + tid * LPAD;

    // O = (4 - c) & 3 : floats of the previous row in the first aligned vector.
    if      (c == 0) run<0>(bt, bt_total, sgn, logm, ops, out, lrow);
    else if (c == 1) run<3>(bt, bt_total, sgn, logm, ops, out, lrow);
    else if (c == 2) run<2>(bt, bt_total, sgn, logm, ops, out, lrow);
    else             run<1>(bt, bt_total, sgn, logm, ops, out, lrow);
}

extern "C" void kernel_launch(void* const* d_in, const int* in_sizes, int n_in,
                              void* d_out, int out_size) {
    const float* sgn  = (const float*)d_in[0];
    const float* logm = (const float*)d_in[1];
    const float* ops  = (const float*)d_in[2];
    float* out = (float*)d_out;

    int bt_total = out_size / 2;                 // 131072; divisible by 4*TPB
    int blocks = bt_total / TPB;
    stack_machine_kernel<<<blocks, TPB>>>(sgn, logm, ops, out, bt_total);
}